// round 1
// baseline (speedup 1.0000x reference)
#include <cuda_runtime.h>
#include <cstdint>

// Problem constants (fixed shapes per reference setup_inputs)
constexpr int Bc = 8;            // batch
constexpr int Sq = 2048;         // sequence
constexpr int Hd = 1024;         // hidden (== input dim)
constexpr int NL = 4;            // layers
constexpr int Mg = Bc * Sq;      // 16384 GEMM rows
constexpr int Ng = 2 * Hd;       // 2048 GEMM cols (gate | hidden)
constexpr int Kg = Hd;           // 1024 reduction
constexpr int NCH = 16;          // scan chunks along S
constexpr int CHL = Sq / NCH;    // 128 steps per chunk

// Scratch (static device arrays: allocation-free per harness rules)
__device__ float g_gh[(size_t)Mg * Ng];      // 134 MB GEMM output
__device__ float g_bufA[(size_t)Mg * Hd];    // 67 MB ping
__device__ float g_bufB[(size_t)Mg * Hd];    // 67 MB pong
__device__ float g_Ac[Bc * NCH * Hd];        // chunk A-products
__device__ float g_Vc[Bc * NCH * Hd];        // chunk V-aggregates
__device__ float g_Hs[Bc * NCH * Hd];        // chunk-start hidden states

#define DEV_INLINE __device__ __forceinline__

DEV_INLINE float sigf(float x) { return 1.f / (1.f + __expf(-x)); }
// g(x) = relu(x)+0.5 for x>=0 else sigmoid(x)
DEV_INLINE float gfun(float x) { return x >= 0.f ? x + 0.5f : sigf(x); }

// ---------------------------------------------------------------------------
// GEMM: C[m,n] = sum_k A[m,k] * W[n,k] + bias[n]
// A: Mg x Kg row-major (input activations), W: Ng x Kg row-major.
// 128x128 block tile, BK=8, 256 threads, 8x8 per-thread microtile,
// double-buffered shared memory.
// ---------------------------------------------------------------------------
__global__ void __launch_bounds__(256)
gemm_kernel(const float* __restrict__ xin, int src,
            const float* __restrict__ W,
            const float* __restrict__ bias)
{
    const float* Aptr = (src == 0) ? xin : (src == 1 ? g_bufA : g_bufB);

    __shared__ float As[2][8][132];   // [buf][k][row] padded to 132 (16B-aligned rows)
    __shared__ float Bs[2][8][132];

    const int tid = threadIdx.x;
    const int tx  = tid & 15;         // 0..15 -> N microtile
    const int ty  = tid >> 4;         // 0..15 -> M microtile
    const int bx  = blockIdx.x;       // N tile
    const int by  = blockIdx.y;       // M tile

    const float* Ab = Aptr + (size_t)by * 128 * Kg;
    const float* Bb = W    + (size_t)bx * 128 * Kg;

    const int lrow = tid >> 1;        // 0..127
    const int lcol = (tid & 1) * 4;   // 0 or 4

    // Prefetch k-tile 0
    float4 a4 = *(const float4*)(Ab + (size_t)lrow * Kg + lcol);
    float4 b4 = *(const float4*)(Bb + (size_t)lrow * Kg + lcol);
    As[0][lcol + 0][lrow] = a4.x; As[0][lcol + 1][lrow] = a4.y;
    As[0][lcol + 2][lrow] = a4.z; As[0][lcol + 3][lrow] = a4.w;
    Bs[0][lcol + 0][lrow] = b4.x; Bs[0][lcol + 1][lrow] = b4.y;
    Bs[0][lcol + 2][lrow] = b4.z; Bs[0][lcol + 3][lrow] = b4.w;
    __syncthreads();

    float acc[8][8];
#pragma unroll
    for (int i = 0; i < 8; i++)
#pragma unroll
        for (int j = 0; j < 8; j++) acc[i][j] = 0.f;

    int buf = 0;
    for (int kt = 8; kt <= Kg; kt += 8) {
        const bool more = (kt < Kg);
        float4 a4n, b4n;
        if (more) {
            a4n = *(const float4*)(Ab + (size_t)lrow * Kg + kt + lcol);
            b4n = *(const float4*)(Bb + (size_t)lrow * Kg + kt + lcol);
        }
#pragma unroll
        for (int k = 0; k < 8; k++) {
            float4 av0 = *(const float4*)&As[buf][k][ty * 8];
            float4 av1 = *(const float4*)&As[buf][k][ty * 8 + 4];
            float4 bv0 = *(const float4*)&Bs[buf][k][tx * 8];
            float4 bv1 = *(const float4*)&Bs[buf][k][tx * 8 + 4];
            float ar[8] = {av0.x, av0.y, av0.z, av0.w, av1.x, av1.y, av1.z, av1.w};
            float br[8] = {bv0.x, bv0.y, bv0.z, bv0.w, bv1.x, bv1.y, bv1.z, bv1.w};
#pragma unroll
            for (int i = 0; i < 8; i++)
#pragma unroll
                for (int j = 0; j < 8; j++)
                    acc[i][j] = fmaf(ar[i], br[j], acc[i][j]);
        }
        if (more) {
            const int nb = buf ^ 1;
            As[nb][lcol + 0][lrow] = a4n.x; As[nb][lcol + 1][lrow] = a4n.y;
            As[nb][lcol + 2][lrow] = a4n.z; As[nb][lcol + 3][lrow] = a4n.w;
            Bs[nb][lcol + 0][lrow] = b4n.x; Bs[nb][lcol + 1][lrow] = b4n.y;
            Bs[nb][lcol + 2][lrow] = b4n.z; Bs[nb][lcol + 3][lrow] = b4n.w;
            __syncthreads();
            buf = nb;
        }
    }

    const int row0 = by * 128 + ty * 8;
    const int col0 = bx * 128 + tx * 8;
#pragma unroll
    for (int i = 0; i < 8; i++) {
        float* crow = g_gh + (size_t)(row0 + i) * Ng + col0;
#pragma unroll
        for (int j = 0; j < 8; j++)
            crow[j] = acc[i][j] + bias[col0 + j];
    }
}

// ---------------------------------------------------------------------------
// Scan phase A: per (b, chunk, h) compute chunk composition (Aacc, Vacc) s.t.
//   h_end = Aacc * h_start + Vacc
// Step: z = sigmoid(gate); a = 1 - z = sigmoid(-gate); v = z * g(hidden)
// ---------------------------------------------------------------------------
__global__ void __launch_bounds__(256)
scan_phaseA_kernel()
{
    const int idx = blockIdx.x * 256 + threadIdx.x;     // b*NCH*Hd + c*Hd + h
    if (idx >= Bc * NCH * Hd) return;
    const int hch = idx & (Hd - 1);
    const int c   = (idx / Hd) & (NCH - 1);
    const int b   = idx / (Hd * NCH);

    const float* base = g_gh + (size_t)b * Sq * Ng + (size_t)c * CHL * Ng + hch;
    float Aacc = 1.f, Vacc = 0.f;
#pragma unroll 4
    for (int s = 0; s < CHL; s++) {
        const float gate = base[(size_t)s * Ng];
        const float hid  = base[(size_t)s * Ng + Hd];
        const float z = sigf(gate);
        const float a = 1.f - z;
        const float v = z * gfun(hid);
        Aacc = a * Aacc;
        Vacc = fmaf(a, Vacc, v);
    }
    g_Ac[idx] = Aacc;
    g_Vc[idx] = Vacc;
}

// ---------------------------------------------------------------------------
// Scan phase B: per (b, h) prefix over NCH chunk aggregates -> chunk-start h.
// Initial hidden state is g(h_prev) (matches reference log_values[0]).
// ---------------------------------------------------------------------------
__global__ void __launch_bounds__(256)
scan_phaseB_kernel(const float* __restrict__ h0l)     // points at h[layer]
{
    const int idx = blockIdx.x * 256 + threadIdx.x;   // b*Hd + h
    if (idx >= Bc * Hd) return;
    const int hch = idx & (Hd - 1);
    const int b   = idx / Hd;

    float hv = gfun(h0l[idx]);
#pragma unroll
    for (int c = 0; c < NCH; c++) {
        const int o = (b * NCH + c) * Hd + hch;
        g_Hs[o] = hv;
        hv = fmaf(g_Ac[o], hv, g_Vc[o]);
    }
}

// ---------------------------------------------------------------------------
// Scan phase C: replay each chunk from its start state, write out = h + inp
// (residual fused). At s == S-1 also write the pre-residual h to finals.
// ---------------------------------------------------------------------------
__global__ void __launch_bounds__(256)
scan_phaseC_kernel(const float* __restrict__ xin, int src,
                   float* __restrict__ dout, int dstsel,
                   float* __restrict__ finals_l)
{
    const int idx = blockIdx.x * 256 + threadIdx.x;
    if (idx >= Bc * NCH * Hd) return;
    const int hch = idx & (Hd - 1);
    const int c   = (idx / Hd) & (NCH - 1);
    const int b   = idx / (Hd * NCH);

    const float* inp = (src == 0) ? xin : (src == 1 ? g_bufA : g_bufB);
    float* outp = (dstsel == 2) ? dout : (dstsel == 0 ? g_bufA : g_bufB);

    const float* gbase = g_gh + (size_t)b * Sq * Ng + (size_t)c * CHL * Ng + hch;
    const float* ibase = inp  + (size_t)b * Sq * Hd + (size_t)c * CHL * Hd + hch;
    float*       obase = outp + (size_t)b * Sq * Hd + (size_t)c * CHL * Hd + hch;

    float hv = g_Hs[(b * NCH + c) * Hd + hch];
#pragma unroll 4
    for (int s = 0; s < CHL; s++) {
        const float gate = gbase[(size_t)s * Ng];
        const float hid  = gbase[(size_t)s * Ng + Hd];
        const float z = sigf(gate);
        const float a = 1.f - z;
        const float v = z * gfun(hid);
        hv = fmaf(a, hv, v);
        obase[(size_t)s * Hd] = hv + ibase[(size_t)s * Hd];
    }
    if (c == NCH - 1)
        finals_l[b * Hd + hch] = hv;   // pre-residual last hidden state
}

// ---------------------------------------------------------------------------
// Launch: 4 layers of GEMM + 3-phase scan. All launches graph-capturable.
// Inputs (metadata order): x, h, W0, b0, Wl, bl.
// Output: out (B,S,H) followed by finals (L,B,1,H).
// ---------------------------------------------------------------------------
extern "C" void kernel_launch(void* const* d_in, const int* in_sizes, int n_in,
                              void* d_out, int out_size)
{
    const float* x  = (const float*)d_in[0];
    const float* h0 = (const float*)d_in[1];   // (L,B,1,H)
    const float* W0 = (const float*)d_in[2];   // (2H, D)
    const float* b0 = (const float*)d_in[3];   // (2H,)
    const float* Wl = (const float*)d_in[4];   // (L-1, 2H, H)
    const float* bl = (const float*)d_in[5];   // (L-1, 2H)

    float* out    = (float*)d_out;                     // (B,S,H)
    float* finals = out + (size_t)Mg * Hd;             // (L,B,1,H)

    const dim3 gemm_grid(Ng / 128, Mg / 128);          // (16, 128)
    const int nA = (Bc * NCH * Hd + 255) / 256;        // 512 blocks
    const int nB = (Bc * Hd + 255) / 256;              // 32 blocks

    // src/dst selectors: 0 = x (layer input ptr), 1 = g_bufA, 2 = g_bufB
    // dstsel: 0 = g_bufA, 1 = g_bufB, 2 = d_out
    int src = 0;
    for (int l = 0; l < NL; l++) {
        const float* W = (l == 0) ? W0 : Wl + (size_t)(l - 1) * Ng * Hd;
        const float* b = (l == 0) ? b0 : bl + (size_t)(l - 1) * Ng;

        gemm_kernel<<<gemm_grid, 256>>>(x, src, W, b);
        scan_phaseA_kernel<<<nA, 256>>>();
        scan_phaseB_kernel<<<nB, 256>>>(h0 + (size_t)l * Bc * Hd);

        int dstsel;
        if (l == NL - 1) dstsel = 2;                   // final layer -> d_out
        else dstsel = (l & 1) ? 1 : 0;                 // ping-pong A/B

        scan_phaseC_kernel<<<nA, 256>>>(x, src, out, dstsel,
                                        finals + (size_t)l * Bc * Hd);

        src = (dstsel == 2) ? 2 : (dstsel == 0 ? 1 : 2);
    }
    (void)in_sizes; (void)n_in; (void)out_size;
}

// round 3
// speedup vs baseline: 2.6185x; 2.6185x over previous
#include <cuda_runtime.h>
#include <cstdint>

// Problem constants (fixed shapes per reference setup_inputs)
constexpr int Bc = 8;            // batch
constexpr int Sq = 2048;         // sequence
constexpr int Hd = 1024;         // hidden (== input dim)
constexpr int NL = 4;            // layers
constexpr int Mg = Bc * Sq;      // 16384 GEMM rows
constexpr int Ng = 2 * Hd;       // 2048 GEMM cols (gate | hidden)
constexpr int Kg = Hd;           // 1024 reduction
constexpr int NCH = 64;          // scan chunks along S
constexpr int CHL = Sq / NCH;    // 32 steps per chunk

// GEMM tiling
constexpr int BM = 128;
constexpr int BN = 128;
constexpr int BK = 16;
constexpr int NKC = Kg / BK;     // 64 k-chunks
constexpr int SKP = BK + 4;      // smem row stride (floats), 20

// Scratch (static device arrays: allocation-free per harness rules)
__device__ float g_gh[(size_t)Mg * Ng];      // 134 MB GEMM output
__device__ float g_bufA[(size_t)Mg * Hd];    // 67 MB ping
__device__ float g_bufB[(size_t)Mg * Hd];    // 67 MB pong
__device__ float g_Ac[Bc * NCH * Hd];        // chunk A-products
__device__ float g_Vc[Bc * NCH * Hd];        // chunk V-aggregates
__device__ float g_Hs[Bc * NCH * Hd];        // chunk-start hidden states

#define DEV_INLINE __device__ __forceinline__

DEV_INLINE float sigf(float x) { return 1.f / (1.f + __expf(-x)); }
DEV_INLINE float gfun(float x) { return x >= 0.f ? x + 0.5f : sigf(x); }

DEV_INLINE uint32_t f2tf32(float x) {
    uint32_t r;
    asm("cvt.rna.tf32.f32 %0, %1;" : "=r"(r) : "f"(x));
    return r;
}

DEV_INLINE void mma_tf32(float& c0, float& c1, float& c2, float& c3,
                         uint32_t a0, uint32_t a1, uint32_t a2, uint32_t a3,
                         uint32_t b0, uint32_t b1) {
    asm volatile(
        "mma.sync.aligned.m16n8k8.row.col.f32.tf32.tf32.f32 "
        "{%0,%1,%2,%3}, {%4,%5,%6,%7}, {%8,%9}, {%0,%1,%2,%3};"
        : "+f"(c0), "+f"(c1), "+f"(c2), "+f"(c3)
        : "r"(a0), "r"(a1), "r"(a2), "r"(a3), "r"(b0), "r"(b1));
}

// ---------------------------------------------------------------------------
// tf32 mma.sync GEMM: C[m,n] = sum_k A[m,k] * W[n,k]   (bias handled in scan)
// A: Mg x Kg row-major, W: Ng x Kg row-major (== col-major B for mma), C=g_gh.
// 128x128x16 tile, 256 threads, 8 warps (4x2), warp tile 32x64,
// double-buffered SMEM with register prefetch.
// ---------------------------------------------------------------------------
__global__ void __launch_bounds__(256)
gemm_mma_kernel(const float* __restrict__ xin, int src,
                const float* __restrict__ W)
{
    const float* Aall = (src == 0) ? xin : (src == 1 ? g_bufA : g_bufB);

    __shared__ float As[2][BM][SKP];
    __shared__ float Bs[2][BN][SKP];

    const int tid  = threadIdx.x;
    const int warp = tid >> 5;
    const int lane = tid & 31;
    const int wm   = warp >> 1;        // 0..3  (M)
    const int wn   = warp & 1;         // 0..1  (N)
    const int g    = lane >> 2;        // 0..7
    const int q    = lane & 3;         // 0..3

    const float* Ab = Aall + (size_t)blockIdx.y * BM * Kg;
    const float* Bb = W    + (size_t)blockIdx.x * BN * Kg;

    // global load assignment: 2 float4 per operand per thread
    const int r0 = tid >> 2;                 // id = tid      -> row 0..63
    const int r1 = (tid + 256) >> 2;         // id = tid+256  -> row 64..127
    const int c4 = (tid & 3) * 4;            // float4 offset within 16-float row

    float4 pa0, pa1, pb0, pb1;

    auto LOADG = [&](int k0) {
        pa0 = *(const float4*)(Ab + (size_t)r0 * Kg + k0 + c4);
        pa1 = *(const float4*)(Ab + (size_t)r1 * Kg + k0 + c4);
        pb0 = *(const float4*)(Bb + (size_t)r0 * Kg + k0 + c4);
        pb1 = *(const float4*)(Bb + (size_t)r1 * Kg + k0 + c4);
    };
    auto STORES = [&](int buf) {
        uint4 t;
        t.x = f2tf32(pa0.x); t.y = f2tf32(pa0.y); t.z = f2tf32(pa0.z); t.w = f2tf32(pa0.w);
        *(uint4*)&As[buf][r0][c4] = t;
        t.x = f2tf32(pa1.x); t.y = f2tf32(pa1.y); t.z = f2tf32(pa1.z); t.w = f2tf32(pa1.w);
        *(uint4*)&As[buf][r1][c4] = t;
        t.x = f2tf32(pb0.x); t.y = f2tf32(pb0.y); t.z = f2tf32(pb0.z); t.w = f2tf32(pb0.w);
        *(uint4*)&Bs[buf][r0][c4] = t;
        t.x = f2tf32(pb1.x); t.y = f2tf32(pb1.y); t.z = f2tf32(pb1.z); t.w = f2tf32(pb1.w);
        *(uint4*)&Bs[buf][r1][c4] = t;
    };

    float acc[2][8][4];
#pragma unroll
    for (int i = 0; i < 2; i++)
#pragma unroll
        for (int j = 0; j < 8; j++)
#pragma unroll
            for (int e = 0; e < 4; e++) acc[i][j][e] = 0.f;

    LOADG(0);
    STORES(0);
    __syncthreads();

    for (int c = 0; c < NKC; c++) {
        const int buf = c & 1;
        if (c + 1 < NKC) LOADG((c + 1) * BK);

        const uint32_t* Au = (const uint32_t*)&As[buf][0][0];
        const uint32_t* Bu = (const uint32_t*)&Bs[buf][0][0];

#pragma unroll
        for (int ks = 0; ks < 2; ks++) {
            const int k0 = ks * 8;
            uint32_t a[2][4];
#pragma unroll
            for (int mt = 0; mt < 2; mt++) {
                const int m = wm * 32 + mt * 16;
                a[mt][0] = Au[(m + g) * SKP + k0 + q];
                a[mt][1] = Au[(m + g + 8) * SKP + k0 + q];
                a[mt][2] = Au[(m + g) * SKP + k0 + q + 4];
                a[mt][3] = Au[(m + g + 8) * SKP + k0 + q + 4];
            }
            uint32_t b[8][2];
#pragma unroll
            for (int nt = 0; nt < 8; nt++) {
                const int n = wn * 64 + nt * 8;
                b[nt][0] = Bu[(n + g) * SKP + k0 + q];
                b[nt][1] = Bu[(n + g) * SKP + k0 + q + 4];
            }
#pragma unroll
            for (int mt = 0; mt < 2; mt++)
#pragma unroll
                for (int nt = 0; nt < 8; nt++)
                    mma_tf32(acc[mt][nt][0], acc[mt][nt][1],
                             acc[mt][nt][2], acc[mt][nt][3],
                             a[mt][0], a[mt][1], a[mt][2], a[mt][3],
                             b[nt][0], b[nt][1]);
        }

        if (c + 1 < NKC) {
            STORES((c + 1) & 1);
            __syncthreads();
        }
    }

    // epilogue
    const int mbase = blockIdx.y * BM + wm * 32;
    const int nbase = blockIdx.x * BN + wn * 64;
#pragma unroll
    for (int mt = 0; mt < 2; mt++) {
#pragma unroll
        for (int nt = 0; nt < 8; nt++) {
            const int m = mbase + mt * 16 + g;
            const int n = nbase + nt * 8 + 2 * q;
            float2 v0 = make_float2(acc[mt][nt][0], acc[mt][nt][1]);
            float2 v1 = make_float2(acc[mt][nt][2], acc[mt][nt][3]);
            *(float2*)(g_gh + (size_t)m * Ng + n) = v0;
            *(float2*)(g_gh + (size_t)(m + 8) * Ng + n) = v1;
        }
    }
}

// ---------------------------------------------------------------------------
// Scan phase A: per (b, chunk, h) chunk composition: h_end = Aacc*h_start + Vacc
// ---------------------------------------------------------------------------
__global__ void __launch_bounds__(256)
scan_phaseA_kernel(const float* __restrict__ bias)
{
    const int idx = blockIdx.x * 256 + threadIdx.x;     // b*NCH*Hd + c*Hd + h
    if (idx >= Bc * NCH * Hd) return;
    const int hch = idx & (Hd - 1);
    const int c   = (idx / Hd) & (NCH - 1);
    const int b   = idx / (Hd * NCH);

    const float bg = bias[hch];
    const float bh = bias[Hd + hch];

    const float* base = g_gh + (size_t)b * Sq * Ng + (size_t)c * CHL * Ng + hch;
    float Aacc = 1.f, Vacc = 0.f;
#pragma unroll 4
    for (int s = 0; s < CHL; s++) {
        const float gate = base[(size_t)s * Ng] + bg;
        const float hid  = base[(size_t)s * Ng + Hd] + bh;
        const float z = sigf(gate);
        const float a = 1.f - z;
        const float v = z * gfun(hid);
        Aacc = a * Aacc;
        Vacc = fmaf(a, Vacc, v);
    }
    g_Ac[idx] = Aacc;
    g_Vc[idx] = Vacc;
}

// ---------------------------------------------------------------------------
// Scan phase B: per (b, h) serial prefix over NCH chunk aggregates.
// ---------------------------------------------------------------------------
__global__ void __launch_bounds__(256)
scan_phaseB_kernel(const float* __restrict__ h0l)
{
    const int idx = blockIdx.x * 256 + threadIdx.x;   // b*Hd + h
    if (idx >= Bc * Hd) return;
    const int hch = idx & (Hd - 1);
    const int b   = idx / Hd;

    float hv = gfun(h0l[idx]);
#pragma unroll
    for (int c = 0; c < NCH; c++) {
        const int o = (b * NCH + c) * Hd + hch;
        g_Hs[o] = hv;
        hv = fmaf(g_Ac[o], hv, g_Vc[o]);
    }
}

// ---------------------------------------------------------------------------
// Scan phase C: replay chunks, fused residual, finals extraction.
// ---------------------------------------------------------------------------
__global__ void __launch_bounds__(256)
scan_phaseC_kernel(const float* __restrict__ xin, int src,
                   float* __restrict__ dout, int dstsel,
                   float* __restrict__ finals_l,
                   const float* __restrict__ bias)
{
    const int idx = blockIdx.x * 256 + threadIdx.x;
    if (idx >= Bc * NCH * Hd) return;
    const int hch = idx & (Hd - 1);
    const int c   = (idx / Hd) & (NCH - 1);
    const int b   = idx / (Hd * NCH);

    const float* inp = (src == 0) ? xin : (src == 1 ? g_bufA : g_bufB);
    float* outp = (dstsel == 2) ? dout : (dstsel == 0 ? g_bufA : g_bufB);

    const float bg = bias[hch];
    const float bh = bias[Hd + hch];

    const float* gbase = g_gh + (size_t)b * Sq * Ng + (size_t)c * CHL * Ng + hch;
    const float* ibase = inp  + (size_t)b * Sq * Hd + (size_t)c * CHL * Hd + hch;
    float*       obase = outp + (size_t)b * Sq * Hd + (size_t)c * CHL * Hd + hch;

    float hv = g_Hs[(b * NCH + c) * Hd + hch];
#pragma unroll 4
    for (int s = 0; s < CHL; s++) {
        const float gate = gbase[(size_t)s * Ng] + bg;
        const float hid  = gbase[(size_t)s * Ng + Hd] + bh;
        const float z = sigf(gate);
        const float a = 1.f - z;
        const float v = z * gfun(hid);
        hv = fmaf(a, hv, v);
        obase[(size_t)s * Hd] = hv + ibase[(size_t)s * Hd];
    }
    if (c == NCH - 1)
        finals_l[b * Hd + hch] = hv;
}

// ---------------------------------------------------------------------------
// Launch: 4 layers of (tf32 mma GEMM + 3-phase scan).
// Inputs (metadata order): x, h, W0, b0, Wl, bl.
// Output: out (B,S,H) followed by finals (L,B,1,H).
// ---------------------------------------------------------------------------
extern "C" void kernel_launch(void* const* d_in, const int* in_sizes, int n_in,
                              void* d_out, int out_size)
{
    const float* x  = (const float*)d_in[0];
    const float* h0 = (const float*)d_in[1];
    const float* W0 = (const float*)d_in[2];
    const float* b0 = (const float*)d_in[3];
    const float* Wl = (const float*)d_in[4];
    const float* bl = (const float*)d_in[5];

    float* out    = (float*)d_out;
    float* finals = out + (size_t)Mg * Hd;

    const dim3 gemm_grid(Ng / BN, Mg / BM);            // (16, 128)
    const int nA = (Bc * NCH * Hd + 255) / 256;        // 2048 blocks
    const int nB = (Bc * Hd + 255) / 256;              // 32 blocks

    int src = 0;
    for (int l = 0; l < NL; l++) {
        const float* W = (l == 0) ? W0 : Wl + (size_t)(l - 1) * Ng * Hd;
        const float* b = (l == 0) ? b0 : bl + (size_t)(l - 1) * Ng;

        gemm_mma_kernel<<<gemm_grid, 256>>>(x, src, W);
        scan_phaseA_kernel<<<nA, 256>>>(b);
        scan_phaseB_kernel<<<nB, 256>>>(h0 + (size_t)l * Bc * Hd);

        int dstsel;
        if (l == NL - 1) dstsel = 2;
        else dstsel = (l & 1) ? 1 : 0;

        scan_phaseC_kernel<<<nA, 256>>>(x, src, out, dstsel,
                                        finals + (size_t)l * Bc * Hd, b);

        src = (dstsel == 2) ? 2 : (dstsel == 0 ? 1 : 2);
    }
    (void)in_sizes; (void)n_in; (void)out_size;
}

// round 8
// speedup vs baseline: 2.8593x; 1.0919x over previous
#include <cuda_runtime.h>
#include <cstdint>

// Problem constants (fixed shapes per reference setup_inputs)
constexpr int Bc = 8;            // batch
constexpr int Sq = 2048;         // sequence
constexpr int Hd = 1024;         // hidden (== input dim)
constexpr int NL = 4;            // layers
constexpr int Mg = Bc * Sq;      // 16384 GEMM rows
constexpr int Ng = 2 * Hd;       // 2048 GEMM cols (gate | hidden)
constexpr int Kg = Hd;           // 1024 reduction
constexpr int NCH = 64;          // scan chunks along S
constexpr int CHL = Sq / NCH;    // 32 steps per chunk

// GEMM tiling
constexpr int BM = 128;
constexpr int BN = 256;
constexpr int BK = 16;
constexpr int NKC = Kg / BK;     // 64 k-chunks
constexpr int SKP = BK + 4;      // smem row stride (floats) = 20
constexpr int STAGES = 4;
constexpr int ASTG = BM * SKP * 4;            // 10240 B per A stage
constexpr int BSTG = BN * SKP * 4;            // 20480 B per B stage
constexpr int SM_B0 = STAGES * ASTG;          // 40960
constexpr int SMEM_DYN = SM_B0 + STAGES * BSTG;  // 122880

// Scratch (static device arrays: allocation-free per harness rules)
__device__ float g_gh[(size_t)Mg * Ng];      // 134 MB GEMM output
__device__ float g_bufA[(size_t)Mg * Hd];    // ping (full-precision out)
__device__ float g_bufB[(size_t)Mg * Hd];    // pong
__device__ float g_rX[(size_t)Mg * Hd];      // tf32-rounded GEMM input
__device__ float g_rW[(size_t)NL * Ng * Kg]; // tf32-rounded weights (32 MB)
__device__ float g_Ac[Bc * NCH * Hd];        // chunk A-products
__device__ float g_Vc[Bc * NCH * Hd];        // chunk V-aggregates
__device__ float g_Hs[Bc * NCH * Hd];        // chunk-start hidden states

#define DEV_INLINE __device__ __forceinline__

DEV_INLINE float sigf(float x) { return 1.f / (1.f + __expf(-x)); }
DEV_INLINE float gfun(float x) { return x >= 0.f ? x + 0.5f : sigf(x); }

DEV_INLINE float f2tf32f(float x) {
    uint32_t r;
    asm("cvt.rna.tf32.f32 %0, %1;" : "=r"(r) : "f"(x));
    return __uint_as_float(r);
}

DEV_INLINE void mma_tf32(float& c0, float& c1, float& c2, float& c3,
                         uint32_t a0, uint32_t a1, uint32_t a2, uint32_t a3,
                         uint32_t b0, uint32_t b1) {
    asm volatile(
        "mma.sync.aligned.m16n8k8.row.col.f32.tf32.tf32.f32 "
        "{%0,%1,%2,%3}, {%4,%5,%6,%7}, {%8,%9}, {%0,%1,%2,%3};"
        : "+f"(c0), "+f"(c1), "+f"(c2), "+f"(c3)
        : "r"(a0), "r"(a1), "r"(a2), "r"(a3), "r"(b0), "r"(b1));
}

#define LDSM4(r, addr) \
    asm volatile("ldmatrix.sync.aligned.m8n8.x4.shared.b16 {%0,%1,%2,%3}, [%4];" \
        : "=r"((r)[0]), "=r"((r)[1]), "=r"((r)[2]), "=r"((r)[3]) : "r"(addr))

#define CP_ASYNC16(dst, src) \
    asm volatile("cp.async.cg.shared.global [%0], [%1], 16;" :: "r"(dst), "l"(src))
#define CP_COMMIT() asm volatile("cp.async.commit_group;" ::: "memory")
#define CP_WAIT(n)  asm volatile("cp.async.wait_group %0;" :: "n"(n) : "memory")

DEV_INLINE uint32_t smem_u32(const void* p) {
    uint32_t a;
    asm("{ .reg .u64 t; cvta.to.shared.u64 t, %1; cvt.u32.u64 %0, t; }"
        : "=r"(a) : "l"(p));
    return a;
}

// ---------------------------------------------------------------------------
// Pre-round weights to tf32 (RNA) once.
// ---------------------------------------------------------------------------
__global__ void __launch_bounds__(256)
round_w_kernel(const float* __restrict__ W0, const float* __restrict__ Wl)
{
    const size_t id4 = (size_t)blockIdx.x * 256 + threadIdx.x;
    const size_t e = id4 * 4;
    if (e >= (size_t)NL * Ng * Kg) return;
    const size_t per = (size_t)Ng * Kg;
    const float* src = (e < per) ? (W0 + e) : (Wl + (e - per));
    float4 v = *(const float4*)src;
    v.x = f2tf32f(v.x); v.y = f2tf32f(v.y); v.z = f2tf32f(v.z); v.w = f2tf32f(v.w);
    *(float4*)(g_rW + e) = v;
}

// Pre-round layer-0 input x to tf32.
__global__ void __launch_bounds__(256)
round_x_kernel(const float* __restrict__ x)
{
    const size_t id4 = (size_t)blockIdx.x * 256 + threadIdx.x;
    const size_t e = id4 * 4;
    if (e >= (size_t)Mg * Hd) return;
    float4 v = *(const float4*)(x + e);
    v.x = f2tf32f(v.x); v.y = f2tf32f(v.y); v.z = f2tf32f(v.z); v.w = f2tf32f(v.w);
    *(float4*)(g_rX + e) = v;
}

// ---------------------------------------------------------------------------
// tf32 mma GEMM: g_gh[m,n] = sum_k g_rX[m,k] * g_rW[wsel][n,k]
// 128x256x16 tile, 256 threads (8 warps, 2x4, warp tile 64x64),
// 4-stage cp.async pipeline, ldmatrix.x4 fragment loads.
// ---------------------------------------------------------------------------
__global__ void __launch_bounds__(256, 1)
gemm_mma_kernel(int wsel)
{
    extern __shared__ char smem[];
    const uint32_t sbase = smem_u32(smem);

    const int tid  = threadIdx.x;
    const int warp = tid >> 5;
    const int lane = tid & 31;
    const int wm   = warp & 1;         // 0..1 (M, 64 rows each)
    const int wn   = warp >> 1;        // 0..3 (N, 64 cols each)
    const int gl   = lane >> 2;        // 0..7
    const int q    = lane & 3;         // 0..3

    const float* Ab = g_rX + (size_t)blockIdx.y * BM * Kg;
    const float* Bb = g_rW + (size_t)wsel * Ng * Kg + (size_t)blockIdx.x * BN * Kg;

    // ldmatrix per-lane address pieces
    const int lrow = (lane & 7) + ((lane >> 3) & 1) * 8;   // 0..15
    const int lkw  = (lane >> 4) * 4;                      // 0 or 4
    uint32_t aoff[4], boff[4];
#pragma unroll
    for (int mt = 0; mt < 4; mt++)
        aoff[mt] = ((wm * 64 + mt * 16 + lrow) * SKP + lkw) * 4;
#pragma unroll
    for (int np = 0; np < 4; np++)
        boff[np] = ((wn * 64 + np * 16 + lrow) * SKP + lkw) * 4;

    float acc[4][8][4];
#pragma unroll
    for (int i = 0; i < 4; i++)
#pragma unroll
        for (int j = 0; j < 8; j++)
#pragma unroll
            for (int e = 0; e < 4; e++) acc[i][j][e] = 0.f;

    auto issue = [&](int slot, int c) {
        const int k0 = c * BK;
#pragma unroll
        for (int i = 0; i < 2; i++) {           // A: 512 16B chunks / 256 thr
            const int id = tid + i * 256;
            const int r  = id >> 2;
            const int cc = id & 3;
            CP_ASYNC16(sbase + slot * ASTG + (r * SKP + cc * 4) * 4,
                       Ab + (size_t)r * Kg + k0 + cc * 4);
        }
#pragma unroll
        for (int i = 0; i < 4; i++) {           // B: 1024 chunks / 256 thr
            const int id = tid + i * 256;
            const int r  = id >> 2;
            const int cc = id & 3;
            CP_ASYNC16(sbase + SM_B0 + slot * BSTG + (r * SKP + cc * 4) * 4,
                       Bb + (size_t)r * Kg + k0 + cc * 4);
        }
    };

    // prologue: fill STAGES-1 stages
#pragma unroll
    for (int s = 0; s < STAGES - 1; s++) { issue(s, s); CP_COMMIT(); }

    for (int c = 0; c < NKC; c++) {
        CP_WAIT(STAGES - 2);
        __syncthreads();

        const int cn = c + STAGES - 1;
        if (cn < NKC) issue(cn % STAGES, cn);
        CP_COMMIT();

        const int slot = c % STAGES;
        const uint32_t as0 = sbase + slot * ASTG;
        const uint32_t bs0 = sbase + SM_B0 + slot * BSTG;
#pragma unroll
        for (int ks = 0; ks < 2; ks++) {
            uint32_t a[4][4], b[4][4];
#pragma unroll
            for (int mt = 0; mt < 4; mt++) LDSM4(a[mt], as0 + aoff[mt] + ks * 32);
#pragma unroll
            for (int np = 0; np < 4; np++) LDSM4(b[np], bs0 + boff[np] + ks * 32);
#pragma unroll
            for (int mt = 0; mt < 4; mt++) {
#pragma unroll
                for (int np = 0; np < 4; np++) {
                    mma_tf32(acc[mt][2*np][0], acc[mt][2*np][1],
                             acc[mt][2*np][2], acc[mt][2*np][3],
                             a[mt][0], a[mt][1], a[mt][2], a[mt][3],
                             b[np][0], b[np][2]);
                    mma_tf32(acc[mt][2*np+1][0], acc[mt][2*np+1][1],
                             acc[mt][2*np+1][2], acc[mt][2*np+1][3],
                             a[mt][0], a[mt][1], a[mt][2], a[mt][3],
                             b[np][1], b[np][3]);
                }
            }
        }
    }

    // epilogue: streaming stores (g_gh read once downstream)
    const int mbase = blockIdx.y * BM + wm * 64;
    const int nbase = blockIdx.x * BN + wn * 64;
#pragma unroll
    for (int mt = 0; mt < 4; mt++) {
#pragma unroll
        for (int nt = 0; nt < 8; nt++) {
            const int m = mbase + mt * 16 + gl;
            const int n = nbase + nt * 8 + 2 * q;
            __stcs((float2*)(g_gh + (size_t)m * Ng + n),
                   make_float2(acc[mt][nt][0], acc[mt][nt][1]));
            __stcs((float2*)(g_gh + (size_t)(m + 8) * Ng + n),
                   make_float2(acc[mt][nt][2], acc[mt][nt][3]));
        }
    }
}

// ---------------------------------------------------------------------------
// Scan phase A (float2): chunk composition h_end = Aacc*h_start + Vacc
// ---------------------------------------------------------------------------
__global__ void __launch_bounds__(256)
scan_phaseA_kernel(const float* __restrict__ bias)
{
    constexpr int H2 = Hd / 2;
    const int idx = blockIdx.x * 256 + threadIdx.x;     // over Bc*NCH*H2
    if (idx >= Bc * NCH * H2) return;
    const int h2 = (idx & (H2 - 1)) * 2;
    const int c  = (idx / H2) & (NCH - 1);
    const int b  = idx / (H2 * NCH);

    const float2 bg = *(const float2*)(bias + h2);
    const float2 bh = *(const float2*)(bias + Hd + h2);

    const float* base = g_gh + (size_t)b * Sq * Ng + (size_t)c * CHL * Ng + h2;
    float Ax = 1.f, Ay = 1.f, Vx = 0.f, Vy = 0.f;
#pragma unroll 8
    for (int s = 0; s < CHL; s++) {
        const float2 gt = __ldcs((const float2*)(base + (size_t)s * Ng));
        const float2 hi = __ldcs((const float2*)(base + (size_t)s * Ng + Hd));
        float zx = sigf(gt.x + bg.x), zy = sigf(gt.y + bg.y);
        float ax = 1.f - zx,          ay = 1.f - zy;
        float vx = zx * gfun(hi.x + bh.x), vy = zy * gfun(hi.y + bh.y);
        Ax = ax * Ax;  Vx = fmaf(ax, Vx, vx);
        Ay = ay * Ay;  Vy = fmaf(ay, Vy, vy);
    }
    const int o = (b * NCH + c) * Hd + h2;
    *(float2*)(g_Ac + o) = make_float2(Ax, Ay);
    *(float2*)(g_Vc + o) = make_float2(Vx, Vy);
}

// ---------------------------------------------------------------------------
// Scan phase B: per (b, h) serial prefix over NCH chunk aggregates.
// ---------------------------------------------------------------------------
__global__ void __launch_bounds__(256)
scan_phaseB_kernel(const float* __restrict__ h0l)
{
    const int idx = blockIdx.x * 256 + threadIdx.x;   // b*Hd + h
    if (idx >= Bc * Hd) return;
    const int hch = idx & (Hd - 1);
    const int b   = idx / Hd;

    float hv = gfun(h0l[idx]);
#pragma unroll
    for (int c = 0; c < NCH; c++) {
        const int o = (b * NCH + c) * Hd + hch;
        g_Hs[o] = hv;
        hv = fmaf(g_Ac[o], hv, g_Vc[o]);
    }
}

// ---------------------------------------------------------------------------
// Scan phase C (float2): replay chunks, fused residual, finals, and
// tf32-rounded copy of the output (next layer's GEMM input).
// ---------------------------------------------------------------------------
__global__ void __launch_bounds__(256)
scan_phaseC_kernel(const float* __restrict__ xin, int src,
                   float* __restrict__ dout, int dstsel,
                   float* __restrict__ finals_l,
                   const float* __restrict__ bias, int wround)
{
    constexpr int H2 = Hd / 2;
    const int idx = blockIdx.x * 256 + threadIdx.x;
    if (idx >= Bc * NCH * H2) return;
    const int h2 = (idx & (H2 - 1)) * 2;
    const int c  = (idx / H2) & (NCH - 1);
    const int b  = idx / (H2 * NCH);

    const float* inp = (src == 0) ? xin : (src == 1 ? g_bufA : g_bufB);
    float* outp = (dstsel == 2) ? dout : (dstsel == 0 ? g_bufA : g_bufB);

    const float2 bg = *(const float2*)(bias + h2);
    const float2 bh = *(const float2*)(bias + Hd + h2);

    const size_t eoff = (size_t)b * Sq * Hd + (size_t)c * CHL * Hd + h2;
    const float* gbase = g_gh + (size_t)b * Sq * Ng + (size_t)c * CHL * Ng + h2;
    const float* ibase = inp + eoff;
    float*       obase = outp + eoff;
    float*       rbase = g_rX + eoff;

    const int o = (b * NCH + c) * Hd + h2;
    float hx = g_Hs[o], hy = g_Hs[o + 1];
#pragma unroll 8
    for (int s = 0; s < CHL; s++) {
        const float2 gt = __ldcs((const float2*)(gbase + (size_t)s * Ng));
        const float2 hi = __ldcs((const float2*)(gbase + (size_t)s * Ng + Hd));
        float zx = sigf(gt.x + bg.x), zy = sigf(gt.y + bg.y);
        float vx = zx * gfun(hi.x + bh.x), vy = zy * gfun(hi.y + bh.y);
        hx = fmaf(1.f - zx, hx, vx);
        hy = fmaf(1.f - zy, hy, vy);
        const float2 iv = *(const float2*)(ibase + (size_t)s * Hd);
        const float ox = hx + iv.x, oy = hy + iv.y;
        *(float2*)(obase + (size_t)s * Hd) = make_float2(ox, oy);
        if (wround)
            __stcs((float2*)(rbase + (size_t)s * Hd),
                   make_float2(f2tf32f(ox), f2tf32f(oy)));
    }
    if (c == NCH - 1)
        *(float2*)(finals_l + b * Hd + h2) = make_float2(hx, hy);
}

// ---------------------------------------------------------------------------
// Launch
// ---------------------------------------------------------------------------
extern "C" void kernel_launch(void* const* d_in, const int* in_sizes, int n_in,
                              void* d_out, int out_size)
{
    const float* x  = (const float*)d_in[0];
    const float* h0 = (const float*)d_in[1];
    const float* W0 = (const float*)d_in[2];
    const float* b0 = (const float*)d_in[3];
    const float* Wl = (const float*)d_in[4];
    const float* bl = (const float*)d_in[5];

    float* out    = (float*)d_out;
    float* finals = out + (size_t)Mg * Hd;

    cudaFuncSetAttribute(gemm_mma_kernel,
                         cudaFuncAttributeMaxDynamicSharedMemorySize, SMEM_DYN);

    const dim3 gemm_grid(Ng / BN, Mg / BM);            // (8, 128)
    const int nAC = (Bc * NCH * (Hd / 2) + 255) / 256; // 1024 blocks
    const int nB  = (Bc * Hd + 255) / 256;             // 32 blocks

    round_w_kernel<<<((size_t)NL * Ng * Kg / 4 + 255) / 256, 256>>>(W0, Wl);
    round_x_kernel<<<((size_t)Mg * Hd / 4 + 255) / 256, 256>>>(x);

    int src = 0;
    for (int l = 0; l < NL; l++) {
        const float* b = (l == 0) ? b0 : bl + (size_t)(l - 1) * Ng;

        gemm_mma_kernel<<<gemm_grid, 256, SMEM_DYN>>>(l);
        scan_phaseA_kernel<<<nAC, 256>>>(b);
        scan_phaseB_kernel<<<nB, 256>>>(h0 + (size_t)l * Bc * Hd);

        int dstsel;
        if (l == NL - 1) dstsel = 2;
        else dstsel = (l & 1) ? 1 : 0;

        scan_phaseC_kernel<<<nAC, 256>>>(x, src, out, dstsel,
                                         finals + (size_t)l * Bc * Hd, b,
                                         (l < NL - 1) ? 1 : 0);

        src = (dstsel == 2) ? 2 : (dstsel == 0 ? 1 : 2);
    }
    (void)in_sizes; (void)n_in; (void)out_size;
}

// round 14
// speedup vs baseline: 4.4174x; 1.5449x over previous
#include <cuda_runtime.h>
#include <cuda_fp16.h>
#include <cstdint>

// Problem constants (fixed shapes per reference setup_inputs)
constexpr int Bc = 8;            // batch
constexpr int Sq = 2048;         // sequence
constexpr int Hd = 1024;         // hidden (== input dim)
constexpr int NL = 4;            // layers
constexpr int Mg = Bc * Sq;      // 16384 GEMM rows
constexpr int Ng = 2 * Hd;       // 2048 GEMM cols (gate | hidden)
constexpr int Kg = Hd;           // 1024 reduction
constexpr int NCH = 64;          // scan chunks along S
constexpr int CHL = Sq / NCH;    // 32 steps per chunk

// GEMM tiling (fp16 operands, fp32 accumulate)
constexpr int BM = 128;
constexpr int BN = 256;
constexpr int BK = 32;           // halves per k-chunk
constexpr int NKC = Kg / BK;     // 32 k-chunks
constexpr int SKPH = 40;         // smem row stride in halves (80 B)
constexpr int STAGES = 4;
constexpr int ASTG = BM * SKPH * 2;           // 10240 B per A stage
constexpr int BSTG = BN * SKPH * 2;           // 20480 B per B stage
constexpr int SM_B0 = STAGES * ASTG;          // 40960
constexpr int SMEM_DYN = SM_B0 + STAGES * BSTG;  // 122880

// Scratch (static device arrays: allocation-free per harness rules)
__device__ float  g_gh[(size_t)Mg * Ng];      // 134 MB GEMM output (fp32)
__device__ float  g_bufA[(size_t)Mg * Hd];    // ping (full-precision out)
__device__ float  g_bufB[(size_t)Mg * Hd];    // pong
__device__ __half g_rX[(size_t)Mg * Hd];      // fp16 GEMM input (33 MB)
__device__ __half g_rW[(size_t)NL * Ng * Kg]; // fp16 weights (16 MB)
__device__ float  g_Ac[Bc * NCH * Hd];        // chunk A-products
__device__ float  g_Vc[Bc * NCH * Hd];        // chunk V-aggregates
__device__ float  g_Hs[Bc * NCH * Hd];        // chunk-start hidden states

#define DEV_INLINE __device__ __forceinline__

DEV_INLINE float sigf(float x) { return 1.f / (1.f + __expf(-x)); }
DEV_INLINE float gfun(float x) { return x >= 0.f ? x + 0.5f : sigf(x); }

DEV_INLINE void mma_f16(float& c0, float& c1, float& c2, float& c3,
                        uint32_t a0, uint32_t a1, uint32_t a2, uint32_t a3,
                        uint32_t b0, uint32_t b1) {
    asm volatile(
        "mma.sync.aligned.m16n8k16.row.col.f32.f16.f16.f32 "
        "{%0,%1,%2,%3}, {%4,%5,%6,%7}, {%8,%9}, {%0,%1,%2,%3};"
        : "+f"(c0), "+f"(c1), "+f"(c2), "+f"(c3)
        : "r"(a0), "r"(a1), "r"(a2), "r"(a3), "r"(b0), "r"(b1));
}

#define LDSM4(r, addr) \
    asm volatile("ldmatrix.sync.aligned.m8n8.x4.shared.b16 {%0,%1,%2,%3}, [%4];" \
        : "=r"((r)[0]), "=r"((r)[1]), "=r"((r)[2]), "=r"((r)[3]) : "r"(addr))

#define CP_ASYNC16(dst, src) \
    asm volatile("cp.async.cg.shared.global [%0], [%1], 16;" :: "r"(dst), "l"(src))
#define CP_COMMIT() asm volatile("cp.async.commit_group;" ::: "memory")
#define CP_WAIT(n)  asm volatile("cp.async.wait_group %0;" :: "n"(n) : "memory")

DEV_INLINE uint32_t smem_u32(const void* p) {
    uint32_t a;
    asm("{ .reg .u64 t; cvta.to.shared.u64 t, %1; cvt.u32.u64 %0, t; }"
        : "=r"(a) : "l"(p));
    return a;
}

// ---------------------------------------------------------------------------
// Convert weights to fp16 once. 8 elements per thread.
// ---------------------------------------------------------------------------
__global__ void __launch_bounds__(256)
round_w_kernel(const float* __restrict__ W0, const float* __restrict__ Wl)
{
    const size_t id = (size_t)blockIdx.x * 256 + threadIdx.x;
    const size_t e = id * 8;
    if (e >= (size_t)NL * Ng * Kg) return;
    const size_t per = (size_t)Ng * Kg;
    const float* src = (e < per) ? (W0 + e) : (Wl + (e - per));
    float4 v0 = *(const float4*)src;
    float4 v1 = *(const float4*)(src + 4);
    __half2 h[4];
    h[0] = __floats2half2_rn(v0.x, v0.y);
    h[1] = __floats2half2_rn(v0.z, v0.w);
    h[2] = __floats2half2_rn(v1.x, v1.y);
    h[3] = __floats2half2_rn(v1.z, v1.w);
    *(uint4*)(g_rW + e) = *(const uint4*)h;
}

// Convert layer-0 input x to fp16.
__global__ void __launch_bounds__(256)
round_x_kernel(const float* __restrict__ x)
{
    const size_t id = (size_t)blockIdx.x * 256 + threadIdx.x;
    const size_t e = id * 8;
    if (e >= (size_t)Mg * Hd) return;
    float4 v0 = *(const float4*)(x + e);
    float4 v1 = *(const float4*)(x + e + 4);
    __half2 h[4];
    h[0] = __floats2half2_rn(v0.x, v0.y);
    h[1] = __floats2half2_rn(v0.z, v0.w);
    h[2] = __floats2half2_rn(v1.x, v1.y);
    h[3] = __floats2half2_rn(v1.z, v1.w);
    *(uint4*)(g_rX + e) = *(const uint4*)h;
}

// ---------------------------------------------------------------------------
// fp16 mma GEMM: g_gh[m,n] = sum_k g_rX[m,k] * g_rW[wsel][n,k]  (fp32 accum)
// 128x256x32 tile, 256 threads (8 warps, 2x4, warp tile 64x64),
// 4-stage cp.async pipeline, ldmatrix.x4 fragment loads, m16n8k16 mma.
// ---------------------------------------------------------------------------
__global__ void __launch_bounds__(256, 1)
gemm_mma_kernel(int wsel)
{
    extern __shared__ char smem[];
    const uint32_t sbase = smem_u32(smem);

    const int tid  = threadIdx.x;
    const int warp = tid >> 5;
    const int lane = tid & 31;
    const int wm   = warp & 1;         // 0..1 (M, 64 rows each)
    const int wn   = warp >> 1;        // 0..3 (N, 64 cols each)
    const int gl   = lane >> 2;        // 0..7
    const int q    = lane & 3;         // 0..3

    const __half* Ab = g_rX + (size_t)blockIdx.y * BM * Kg;
    const __half* Bb = g_rW + (size_t)wsel * Ng * Kg + (size_t)blockIdx.x * BN * Kg;

    // ldmatrix per-lane address pieces: lanes 0-15 -> rows 0-15 (first 8
    // k-halves), lanes 16-31 -> same rows, +16B (next 8 k-halves).
    const int lrow = lane & 15;
    const int lcb  = (lane >> 4) * 16;                     // byte col offset
    uint32_t aoff[4], boff[4];
#pragma unroll
    for (int mt = 0; mt < 4; mt++)
        aoff[mt] = (wm * 64 + mt * 16 + lrow) * (SKPH * 2) + lcb;
#pragma unroll
    for (int ng = 0; ng < 4; ng++)
        boff[ng] = (wn * 64 + ng * 16 + lrow) * (SKPH * 2) + lcb;

    float acc[4][8][4];
#pragma unroll
    for (int i = 0; i < 4; i++)
#pragma unroll
        for (int j = 0; j < 8; j++)
#pragma unroll
            for (int e = 0; e < 4; e++) acc[i][j][e] = 0.f;

    auto issue = [&](int slot, int c) {
        const int k0 = c * BK;
#pragma unroll
        for (int i = 0; i < 2; i++) {           // A: 512 16B chunks / 256 thr
            const int id = tid + i * 256;
            const int r  = id >> 2;
            const int cc = id & 3;
            CP_ASYNC16(sbase + slot * ASTG + r * (SKPH * 2) + cc * 16,
                       Ab + (size_t)r * Kg + k0 + cc * 8);
        }
#pragma unroll
        for (int i = 0; i < 4; i++) {           // B: 1024 chunks / 256 thr
            const int id = tid + i * 256;
            const int r  = id >> 2;
            const int cc = id & 3;
            CP_ASYNC16(sbase + SM_B0 + slot * BSTG + r * (SKPH * 2) + cc * 16,
                       Bb + (size_t)r * Kg + k0 + cc * 8);
        }
    };

    // prologue: fill STAGES-1 stages
#pragma unroll
    for (int s = 0; s < STAGES - 1; s++) { issue(s, s); CP_COMMIT(); }

    for (int c = 0; c < NKC; c++) {
        CP_WAIT(STAGES - 2);
        __syncthreads();

        const int cn = c + STAGES - 1;
        if (cn < NKC) issue(cn % STAGES, cn);
        CP_COMMIT();

        const int slot = c % STAGES;
        const uint32_t as0 = sbase + slot * ASTG;
        const uint32_t bs0 = sbase + SM_B0 + slot * BSTG;
#pragma unroll
        for (int ks = 0; ks < 2; ks++) {        // two k=16 steps per chunk
            uint32_t a[4][4], b[4][4];
#pragma unroll
            for (int mt = 0; mt < 4; mt++) LDSM4(a[mt], as0 + aoff[mt] + ks * 32);
#pragma unroll
            for (int ng = 0; ng < 4; ng++) LDSM4(b[ng], bs0 + boff[ng] + ks * 32);
#pragma unroll
            for (int mt = 0; mt < 4; mt++) {
#pragma unroll
                for (int ng = 0; ng < 4; ng++) {
                    mma_f16(acc[mt][2*ng][0], acc[mt][2*ng][1],
                            acc[mt][2*ng][2], acc[mt][2*ng][3],
                            a[mt][0], a[mt][1], a[mt][2], a[mt][3],
                            b[ng][0], b[ng][2]);
                    mma_f16(acc[mt][2*ng+1][0], acc[mt][2*ng+1][1],
                            acc[mt][2*ng+1][2], acc[mt][2*ng+1][3],
                            a[mt][0], a[mt][1], a[mt][2], a[mt][3],
                            b[ng][1], b[ng][3]);
                }
            }
        }
    }

    // epilogue: streaming stores (g_gh read once downstream)
    const int mbase = blockIdx.y * BM + wm * 64;
    const int nbase = blockIdx.x * BN + wn * 64;
#pragma unroll
    for (int mt = 0; mt < 4; mt++) {
#pragma unroll
        for (int nt = 0; nt < 8; nt++) {
            const int m = mbase + mt * 16 + gl;
            const int n = nbase + nt * 8 + 2 * q;
            __stcs((float2*)(g_gh + (size_t)m * Ng + n),
                   make_float2(acc[mt][nt][0], acc[mt][nt][1]));
            __stcs((float2*)(g_gh + (size_t)(m + 8) * Ng + n),
                   make_float2(acc[mt][nt][2], acc[mt][nt][3]));
        }
    }
}

// ---------------------------------------------------------------------------
// Scan phase A (float2): chunk composition h_end = Aacc*h_start + Vacc
// ---------------------------------------------------------------------------
__global__ void __launch_bounds__(256)
scan_phaseA_kernel(const float* __restrict__ bias)
{
    constexpr int H2 = Hd / 2;
    const int idx = blockIdx.x * 256 + threadIdx.x;     // over Bc*NCH*H2
    if (idx >= Bc * NCH * H2) return;
    const int h2 = (idx & (H2 - 1)) * 2;
    const int c  = (idx / H2) & (NCH - 1);
    const int b  = idx / (H2 * NCH);

    const float2 bg = *(const float2*)(bias + h2);
    const float2 bh = *(const float2*)(bias + Hd + h2);

    const float* base = g_gh + (size_t)b * Sq * Ng + (size_t)c * CHL * Ng + h2;
    float Ax = 1.f, Ay = 1.f, Vx = 0.f, Vy = 0.f;
#pragma unroll 8
    for (int s = 0; s < CHL; s++) {
        const float2 gt = __ldcs((const float2*)(base + (size_t)s * Ng));
        const float2 hi = __ldcs((const float2*)(base + (size_t)s * Ng + Hd));
        float zx = sigf(gt.x + bg.x), zy = sigf(gt.y + bg.y);
        float ax = 1.f - zx,          ay = 1.f - zy;
        float vx = zx * gfun(hi.x + bh.x), vy = zy * gfun(hi.y + bh.y);
        Ax = ax * Ax;  Vx = fmaf(ax, Vx, vx);
        Ay = ay * Ay;  Vy = fmaf(ay, Vy, vy);
    }
    const int o = (b * NCH + c) * Hd + h2;
    *(float2*)(g_Ac + o) = make_float2(Ax, Ay);
    *(float2*)(g_Vc + o) = make_float2(Vx, Vy);
}

// ---------------------------------------------------------------------------
// Scan phase B: per (b, h) serial prefix over NCH chunk aggregates.
// ---------------------------------------------------------------------------
__global__ void __launch_bounds__(256)
scan_phaseB_kernel(const float* __restrict__ h0l)
{
    const int idx = blockIdx.x * 256 + threadIdx.x;   // b*Hd + h
    if (idx >= Bc * Hd) return;
    const int hch = idx & (Hd - 1);
    const int b   = idx / Hd;

    float hv = gfun(h0l[idx]);
#pragma unroll
    for (int c = 0; c < NCH; c++) {
        const int o = (b * NCH + c) * Hd + hch;
        g_Hs[o] = hv;
        hv = fmaf(g_Ac[o], hv, g_Vc[o]);
    }
}

// ---------------------------------------------------------------------------
// Scan phase C (float2): replay chunks, fused residual, finals, and
// fp16 copy of the output (next layer's GEMM input).
// ---------------------------------------------------------------------------
__global__ void __launch_bounds__(256)
scan_phaseC_kernel(const float* __restrict__ xin, int src,
                   float* __restrict__ dout, int dstsel,
                   float* __restrict__ finals_l,
                   const float* __restrict__ bias, int wround)
{
    constexpr int H2 = Hd / 2;
    const int idx = blockIdx.x * 256 + threadIdx.x;
    if (idx >= Bc * NCH * H2) return;
    const int h2 = (idx & (H2 - 1)) * 2;
    const int c  = (idx / H2) & (NCH - 1);
    const int b  = idx / (H2 * NCH);

    const float* inp = (src == 0) ? xin : (src == 1 ? g_bufA : g_bufB);
    float* outp = (dstsel == 2) ? dout : (dstsel == 0 ? g_bufA : g_bufB);

    const float2 bg = *(const float2*)(bias + h2);
    const float2 bh = *(const float2*)(bias + Hd + h2);

    const size_t eoff = (size_t)b * Sq * Hd + (size_t)c * CHL * Hd + h2;
    const float* gbase = g_gh + (size_t)b * Sq * Ng + (size_t)c * CHL * Ng + h2;
    const float* ibase = inp + eoff;
    float*       obase = outp + eoff;
    __half*      rbase = g_rX + eoff;

    const int o = (b * NCH + c) * Hd + h2;
    float hx = g_Hs[o], hy = g_Hs[o + 1];
#pragma unroll 8
    for (int s = 0; s < CHL; s++) {
        const float2 gt = __ldcs((const float2*)(gbase + (size_t)s * Ng));
        const float2 hi = __ldcs((const float2*)(gbase + (size_t)s * Ng + Hd));
        float zx = sigf(gt.x + bg.x), zy = sigf(gt.y + bg.y);
        float vx = zx * gfun(hi.x + bh.x), vy = zy * gfun(hi.y + bh.y);
        hx = fmaf(1.f - zx, hx, vx);
        hy = fmaf(1.f - zy, hy, vy);
        const float2 iv = *(const float2*)(ibase + (size_t)s * Hd);
        const float ox = hx + iv.x, oy = hy + iv.y;
        *(float2*)(obase + (size_t)s * Hd) = make_float2(ox, oy);
        if (wround)
            *(__half2*)(rbase + (size_t)s * Hd) = __floats2half2_rn(ox, oy);
    }
    if (c == NCH - 1)
        *(float2*)(finals_l + b * Hd + h2) = make_float2(hx, hy);
}

// ---------------------------------------------------------------------------
// Launch
// ---------------------------------------------------------------------------
extern "C" void kernel_launch(void* const* d_in, const int* in_sizes, int n_in,
                              void* d_out, int out_size)
{
    const float* x  = (const float*)d_in[0];
    const float* h0 = (const float*)d_in[1];
    const float* W0 = (const float*)d_in[2];
    const float* b0 = (const float*)d_in[3];
    const float* Wl = (const float*)d_in[4];
    const float* bl = (const float*)d_in[5];

    float* out    = (float*)d_out;
    float* finals = out + (size_t)Mg * Hd;

    cudaFuncSetAttribute(gemm_mma_kernel,
                         cudaFuncAttributeMaxDynamicSharedMemorySize, SMEM_DYN);

    const dim3 gemm_grid(Ng / BN, Mg / BM);            // (8, 128)
    const int nAC = (Bc * NCH * (Hd / 2) + 255) / 256; // 1024 blocks
    const int nB  = (Bc * Hd + 255) / 256;             // 32 blocks

    round_w_kernel<<<((size_t)NL * Ng * Kg / 8 + 255) / 256, 256>>>(W0, Wl);
    round_x_kernel<<<((size_t)Mg * Hd / 8 + 255) / 256, 256>>>(x);

    int src = 0;
    for (int l = 0; l < NL; l++) {
        const float* b = (l == 0) ? b0 : bl + (size_t)(l - 1) * Ng;

        gemm_mma_kernel<<<gemm_grid, 256, SMEM_DYN>>>(l);
        scan_phaseA_kernel<<<nAC, 256>>>(b);
        scan_phaseB_kernel<<<nB, 256>>>(h0 + (size_t)l * Bc * Hd);

        int dstsel;
        if (l == NL - 1) dstsel = 2;
        else dstsel = (l & 1) ? 1 : 0;

        scan_phaseC_kernel<<<nAC, 256>>>(x, src, out, dstsel,
                                         finals + (size_t)l * Bc * Hd, b,
                                         (l < NL - 1) ? 1 : 0);

        src = (dstsel == 2) ? 2 : (dstsel == 0 ? 1 : 2);
    }
    (void)in_sizes; (void)n_in; (void)out_size;
}

// round 15
// speedup vs baseline: 4.5719x; 1.0350x over previous
#include <cuda_runtime.h>
#include <cuda_fp16.h>
#include <cstdint>

// Problem constants (fixed shapes per reference setup_inputs)
constexpr int Bc = 8;            // batch
constexpr int Sq = 2048;         // sequence
constexpr int Hd = 1024;         // hidden (== input dim)
constexpr int NL = 4;            // layers
constexpr int Mg = Bc * Sq;      // 16384 GEMM rows
constexpr int Ng = 2 * Hd;       // 2048 GEMM cols (gate | hidden)
constexpr int Kg = Hd;           // 1024 reduction
constexpr int NCH = 64;          // scan chunks along S
constexpr int CHL = Sq / NCH;    // 32 steps per chunk

// GEMM tiling (fp16 operands, fp32 accumulate)
constexpr int BM = 128;
constexpr int BN = 256;
constexpr int BK = 32;           // halves per k-chunk
constexpr int NKC = Kg / BK;     // 32 k-chunks
constexpr int SKPH = 40;         // smem row stride in halves (80 B)
constexpr int STAGES = 4;
constexpr int ASTG = BM * SKPH * 2;           // 10240 B per A stage
constexpr int BSTG = BN * SKPH * 2;           // 20480 B per B stage
constexpr int SM_B0 = STAGES * ASTG;          // 40960
constexpr int SMEM_DYN = SM_B0 + STAGES * BSTG;  // 122880

// Scratch (static device arrays: allocation-free per harness rules)
__device__ __half g_gh[(size_t)Mg * Ng];      // 67 MB GEMM output (fp16)
__device__ float  g_bufA[(size_t)Mg * Hd];    // ping (full-precision out)
__device__ float  g_bufB[(size_t)Mg * Hd];    // pong
__device__ __half g_rX[(size_t)Mg * Hd];      // fp16 GEMM input (33 MB)
__device__ __half g_rW[(size_t)NL * Ng * Kg]; // fp16 weights (16 MB)
__device__ float  g_Ac[Bc * NCH * Hd];        // chunk A-products
__device__ float  g_Vc[Bc * NCH * Hd];        // chunk V-aggregates
__device__ float  g_Hs[Bc * NCH * Hd];        // chunk-start hidden states

#define DEV_INLINE __device__ __forceinline__

DEV_INLINE float sigf(float x) { return 1.f / (1.f + __expf(-x)); }
DEV_INLINE float gfun(float x) { return x >= 0.f ? x + 0.5f : sigf(x); }

DEV_INLINE float2 ldcs_h2(const __half* p) {
    uint32_t u = __ldcs((const uint32_t*)p);
    __half2 h = *reinterpret_cast<__half2*>(&u);
    return __half22float2(h);
}

DEV_INLINE void mma_f16(float& c0, float& c1, float& c2, float& c3,
                        uint32_t a0, uint32_t a1, uint32_t a2, uint32_t a3,
                        uint32_t b0, uint32_t b1) {
    asm volatile(
        "mma.sync.aligned.m16n8k16.row.col.f32.f16.f16.f32 "
        "{%0,%1,%2,%3}, {%4,%5,%6,%7}, {%8,%9}, {%0,%1,%2,%3};"
        : "+f"(c0), "+f"(c1), "+f"(c2), "+f"(c3)
        : "r"(a0), "r"(a1), "r"(a2), "r"(a3), "r"(b0), "r"(b1));
}

#define LDSM4(r, addr) \
    asm volatile("ldmatrix.sync.aligned.m8n8.x4.shared.b16 {%0,%1,%2,%3}, [%4];" \
        : "=r"((r)[0]), "=r"((r)[1]), "=r"((r)[2]), "=r"((r)[3]) : "r"(addr))

#define CP_ASYNC16(dst, src) \
    asm volatile("cp.async.cg.shared.global [%0], [%1], 16;" :: "r"(dst), "l"(src))
#define CP_COMMIT() asm volatile("cp.async.commit_group;" ::: "memory")
#define CP_WAIT(n)  asm volatile("cp.async.wait_group %0;" :: "n"(n) : "memory")

DEV_INLINE uint32_t smem_u32(const void* p) {
    uint32_t a;
    asm("{ .reg .u64 t; cvta.to.shared.u64 t, %1; cvt.u32.u64 %0, t; }"
        : "=r"(a) : "l"(p));
    return a;
}

// ---------------------------------------------------------------------------
// Convert weights to fp16 once. 8 elements per thread.
// ---------------------------------------------------------------------------
__global__ void __launch_bounds__(256)
round_w_kernel(const float* __restrict__ W0, const float* __restrict__ Wl)
{
    const size_t id = (size_t)blockIdx.x * 256 + threadIdx.x;
    const size_t e = id * 8;
    if (e >= (size_t)NL * Ng * Kg) return;
    const size_t per = (size_t)Ng * Kg;
    const float* src = (e < per) ? (W0 + e) : (Wl + (e - per));
    float4 v0 = *(const float4*)src;
    float4 v1 = *(const float4*)(src + 4);
    __half2 h[4];
    h[0] = __floats2half2_rn(v0.x, v0.y);
    h[1] = __floats2half2_rn(v0.z, v0.w);
    h[2] = __floats2half2_rn(v1.x, v1.y);
    h[3] = __floats2half2_rn(v1.z, v1.w);
    *(uint4*)(g_rW + e) = *(const uint4*)h;
}

// Convert layer-0 input x to fp16.
__global__ void __launch_bounds__(256)
round_x_kernel(const float* __restrict__ x)
{
    const size_t id = (size_t)blockIdx.x * 256 + threadIdx.x;
    const size_t e = id * 8;
    if (e >= (size_t)Mg * Hd) return;
    float4 v0 = *(const float4*)(x + e);
    float4 v1 = *(const float4*)(x + e + 4);
    __half2 h[4];
    h[0] = __floats2half2_rn(v0.x, v0.y);
    h[1] = __floats2half2_rn(v0.z, v0.w);
    h[2] = __floats2half2_rn(v1.x, v1.y);
    h[3] = __floats2half2_rn(v1.z, v1.w);
    *(uint4*)(g_rX + e) = *(const uint4*)h;
}

// ---------------------------------------------------------------------------
// fp16 mma GEMM: g_gh[m,n] = sum_k g_rX[m,k] * g_rW[wsel][n,k]  (fp32 accum,
// fp16 output). 128x256x32 tile, 256 threads (8 warps, 2x4, warp tile 64x64),
// 4-stage cp.async pipeline, ldmatrix.x4 fragment loads, m16n8k16 mma.
// ---------------------------------------------------------------------------
__global__ void __launch_bounds__(256, 1)
gemm_mma_kernel(int wsel)
{
    extern __shared__ char smem[];
    const uint32_t sbase = smem_u32(smem);

    const int tid  = threadIdx.x;
    const int warp = tid >> 5;
    const int lane = tid & 31;
    const int wm   = warp & 1;         // 0..1 (M, 64 rows each)
    const int wn   = warp >> 1;        // 0..3 (N, 64 cols each)
    const int gl   = lane >> 2;        // 0..7
    const int q    = lane & 3;         // 0..3

    const __half* Ab = g_rX + (size_t)blockIdx.y * BM * Kg;
    const __half* Bb = g_rW + (size_t)wsel * Ng * Kg + (size_t)blockIdx.x * BN * Kg;

    // ldmatrix per-lane address pieces: lanes 0-15 -> rows 0-15 (first 8
    // k-halves), lanes 16-31 -> same rows, +16B (next 8 k-halves).
    const int lrow = lane & 15;
    const int lcb  = (lane >> 4) * 16;                     // byte col offset
    uint32_t aoff[4], boff[4];
#pragma unroll
    for (int mt = 0; mt < 4; mt++)
        aoff[mt] = (wm * 64 + mt * 16 + lrow) * (SKPH * 2) + lcb;
#pragma unroll
    for (int ng = 0; ng < 4; ng++)
        boff[ng] = (wn * 64 + ng * 16 + lrow) * (SKPH * 2) + lcb;

    float acc[4][8][4];
#pragma unroll
    for (int i = 0; i < 4; i++)
#pragma unroll
        for (int j = 0; j < 8; j++)
#pragma unroll
            for (int e = 0; e < 4; e++) acc[i][j][e] = 0.f;

    auto issue = [&](int slot, int c) {
        const int k0 = c * BK;
#pragma unroll
        for (int i = 0; i < 2; i++) {           // A: 512 16B chunks / 256 thr
            const int id = tid + i * 256;
            const int r  = id >> 2;
            const int cc = id & 3;
            CP_ASYNC16(sbase + slot * ASTG + r * (SKPH * 2) + cc * 16,
                       Ab + (size_t)r * Kg + k0 + cc * 8);
        }
#pragma unroll
        for (int i = 0; i < 4; i++) {           // B: 1024 chunks / 256 thr
            const int id = tid + i * 256;
            const int r  = id >> 2;
            const int cc = id & 3;
            CP_ASYNC16(sbase + SM_B0 + slot * BSTG + r * (SKPH * 2) + cc * 16,
                       Bb + (size_t)r * Kg + k0 + cc * 8);
        }
    };

    // prologue: fill STAGES-1 stages
#pragma unroll
    for (int s = 0; s < STAGES - 1; s++) { issue(s, s); CP_COMMIT(); }

    for (int c = 0; c < NKC; c++) {
        CP_WAIT(STAGES - 2);
        __syncthreads();

        const int cn = c + STAGES - 1;
        if (cn < NKC) issue(cn % STAGES, cn);
        CP_COMMIT();

        const int slot = c % STAGES;
        const uint32_t as0 = sbase + slot * ASTG;
        const uint32_t bs0 = sbase + SM_B0 + slot * BSTG;
#pragma unroll
        for (int ks = 0; ks < 2; ks++) {        // two k=16 steps per chunk
            uint32_t a[4][4], b[4][4];
#pragma unroll
            for (int mt = 0; mt < 4; mt++) LDSM4(a[mt], as0 + aoff[mt] + ks * 32);
#pragma unroll
            for (int ng = 0; ng < 4; ng++) LDSM4(b[ng], bs0 + boff[ng] + ks * 32);
#pragma unroll
            for (int mt = 0; mt < 4; mt++) {
#pragma unroll
                for (int ng = 0; ng < 4; ng++) {
                    mma_f16(acc[mt][2*ng][0], acc[mt][2*ng][1],
                            acc[mt][2*ng][2], acc[mt][2*ng][3],
                            a[mt][0], a[mt][1], a[mt][2], a[mt][3],
                            b[ng][0], b[ng][2]);
                    mma_f16(acc[mt][2*ng+1][0], acc[mt][2*ng+1][1],
                            acc[mt][2*ng+1][2], acc[mt][2*ng+1][3],
                            a[mt][0], a[mt][1], a[mt][2], a[mt][3],
                            b[ng][1], b[ng][3]);
                }
            }
        }
    }

    // epilogue: fp16 streaming stores (g_gh read once downstream)
    const int mbase = blockIdx.y * BM + wm * 64;
    const int nbase = blockIdx.x * BN + wn * 64;
#pragma unroll
    for (int mt = 0; mt < 4; mt++) {
#pragma unroll
        for (int nt = 0; nt < 8; nt++) {
            const int m = mbase + mt * 16 + gl;
            const int n = nbase + nt * 8 + 2 * q;
            __half2 p0 = __floats2half2_rn(acc[mt][nt][0], acc[mt][nt][1]);
            __half2 p1 = __floats2half2_rn(acc[mt][nt][2], acc[mt][nt][3]);
            __stcs((uint32_t*)(g_gh + (size_t)m * Ng + n),
                   *reinterpret_cast<uint32_t*>(&p0));
            __stcs((uint32_t*)(g_gh + (size_t)(m + 8) * Ng + n),
                   *reinterpret_cast<uint32_t*>(&p1));
        }
    }
}

// ---------------------------------------------------------------------------
// Scan phase A: chunk composition h_end = Aacc*h_start + Vacc  (fp16 gh in)
// ---------------------------------------------------------------------------
__global__ void __launch_bounds__(256)
scan_phaseA_kernel(const float* __restrict__ bias)
{
    constexpr int H2 = Hd / 2;
    const int idx = blockIdx.x * 256 + threadIdx.x;     // over Bc*NCH*H2
    if (idx >= Bc * NCH * H2) return;
    const int h2 = (idx & (H2 - 1)) * 2;
    const int c  = (idx / H2) & (NCH - 1);
    const int b  = idx / (H2 * NCH);

    const float2 bg = *(const float2*)(bias + h2);
    const float2 bh = *(const float2*)(bias + Hd + h2);

    const __half* base = g_gh + (size_t)b * Sq * Ng + (size_t)c * CHL * Ng + h2;
    float Ax = 1.f, Ay = 1.f, Vx = 0.f, Vy = 0.f;
#pragma unroll 8
    for (int s = 0; s < CHL; s++) {
        const float2 gt = ldcs_h2(base + (size_t)s * Ng);
        const float2 hi = ldcs_h2(base + (size_t)s * Ng + Hd);
        float zx = sigf(gt.x + bg.x), zy = sigf(gt.y + bg.y);
        float ax = 1.f - zx,          ay = 1.f - zy;
        float vx = zx * gfun(hi.x + bh.x), vy = zy * gfun(hi.y + bh.y);
        Ax = ax * Ax;  Vx = fmaf(ax, Vx, vx);
        Ay = ay * Ay;  Vy = fmaf(ay, Vy, vy);
    }
    const int o = (b * NCH + c) * Hd + h2;
    *(float2*)(g_Ac + o) = make_float2(Ax, Ay);
    *(float2*)(g_Vc + o) = make_float2(Vx, Vy);
}

// ---------------------------------------------------------------------------
// Scan phase B: per (b, h) serial prefix over NCH chunk aggregates.
// ---------------------------------------------------------------------------
__global__ void __launch_bounds__(256)
scan_phaseB_kernel(const float* __restrict__ h0l)
{
    const int idx = blockIdx.x * 256 + threadIdx.x;   // b*Hd + h
    if (idx >= Bc * Hd) return;
    const int hch = idx & (Hd - 1);
    const int b   = idx / Hd;

    float hv = gfun(h0l[idx]);
#pragma unroll
    for (int c = 0; c < NCH; c++) {
        const int o = (b * NCH + c) * Hd + hch;
        g_Hs[o] = hv;
        hv = fmaf(g_Ac[o], hv, g_Vc[o]);
    }
}

// ---------------------------------------------------------------------------
// Scan phase C: replay chunks, fused residual, finals, and fp16 copy of the
// output (next layer's GEMM input). fp16 gh in.
// ---------------------------------------------------------------------------
__global__ void __launch_bounds__(256)
scan_phaseC_kernel(const float* __restrict__ xin, int src,
                   float* __restrict__ dout, int dstsel,
                   float* __restrict__ finals_l,
                   const float* __restrict__ bias, int wround)
{
    constexpr int H2 = Hd / 2;
    const int idx = blockIdx.x * 256 + threadIdx.x;
    if (idx >= Bc * NCH * H2) return;
    const int h2 = (idx & (H2 - 1)) * 2;
    const int c  = (idx / H2) & (NCH - 1);
    const int b  = idx / (H2 * NCH);

    const float* inp = (src == 0) ? xin : (src == 1 ? g_bufA : g_bufB);
    float* outp = (dstsel == 2) ? dout : (dstsel == 0 ? g_bufA : g_bufB);

    const float2 bg = *(const float2*)(bias + h2);
    const float2 bh = *(const float2*)(bias + Hd + h2);

    const size_t eoff = (size_t)b * Sq * Hd + (size_t)c * CHL * Hd + h2;
    const __half* gbase = g_gh + (size_t)b * Sq * Ng + (size_t)c * CHL * Ng + h2;
    const float* ibase = inp + eoff;
    float*       obase = outp + eoff;
    __half*      rbase = g_rX + eoff;

    const int o = (b * NCH + c) * Hd + h2;
    float hx = g_Hs[o], hy = g_Hs[o + 1];
#pragma unroll 8
    for (int s = 0; s < CHL; s++) {
        const float2 gt = ldcs_h2(gbase + (size_t)s * Ng);
        const float2 hi = ldcs_h2(gbase + (size_t)s * Ng + Hd);
        float zx = sigf(gt.x + bg.x), zy = sigf(gt.y + bg.y);
        float vx = zx * gfun(hi.x + bh.x), vy = zy * gfun(hi.y + bh.y);
        hx = fmaf(1.f - zx, hx, vx);
        hy = fmaf(1.f - zy, hy, vy);
        const float2 iv = *(const float2*)(ibase + (size_t)s * Hd);
        const float ox = hx + iv.x, oy = hy + iv.y;
        *(float2*)(obase + (size_t)s * Hd) = make_float2(ox, oy);
        if (wround) {
            __half2 hv2 = __floats2half2_rn(ox, oy);
            __stcs((uint32_t*)(rbase + (size_t)s * Hd),
                   *reinterpret_cast<uint32_t*>(&hv2));
        }
    }
    if (c == NCH - 1)
        *(float2*)(finals_l + b * Hd + h2) = make_float2(hx, hy);
}

// ---------------------------------------------------------------------------
// Launch
// ---------------------------------------------------------------------------
extern "C" void kernel_launch(void* const* d_in, const int* in_sizes, int n_in,
                              void* d_out, int out_size)
{
    const float* x  = (const float*)d_in[0];
    const float* h0 = (const float*)d_in[1];
    const float* W0 = (const float*)d_in[2];
    const float* b0 = (const float*)d_in[3];
    const float* Wl = (const float*)d_in[4];
    const float* bl = (const float*)d_in[5];

    float* out    = (float*)d_out;
    float* finals = out + (size_t)Mg * Hd;

    cudaFuncSetAttribute(gemm_mma_kernel,
                         cudaFuncAttributeMaxDynamicSharedMemorySize, SMEM_DYN);

    const dim3 gemm_grid(Ng / BN, Mg / BM);            // (8, 128)
    const int nAC = (Bc * NCH * (Hd / 2) + 255) / 256; // 1024 blocks
    const int nB  = (Bc * Hd + 255) / 256;             // 32 blocks

    round_w_kernel<<<((size_t)NL * Ng * Kg / 8 + 255) / 256, 256>>>(W0, Wl);
    round_x_kernel<<<((size_t)Mg * Hd / 8 + 255) / 256, 256>>>(x);

    int src = 0;
    for (int l = 0; l < NL; l++) {
        const float* b = (l == 0) ? b0 : bl + (size_t)(l - 1) * Ng;

        gemm_mma_kernel<<<gemm_grid, 256, SMEM_DYN>>>(l);
        scan_phaseA_kernel<<<nAC, 256>>>(b);
        scan_phaseB_kernel<<<nB, 256>>>(h0 + (size_t)l * Bc * Hd);

        int dstsel;
        if (l == NL - 1) dstsel = 2;
        else dstsel = (l & 1) ? 1 : 0;

        scan_phaseC_kernel<<<nAC, 256>>>(x, src, out, dstsel,
                                         finals + (size_t)l * Bc * Hd, b,
                                         (l < NL - 1) ? 1 : 0);

        src = (dstsel == 2) ? 2 : (dstsel == 0 ? 1 : 2);
    }
    (void)in_sizes; (void)n_in; (void)out_size;
}